// round 16
// baseline (speedup 1.0000x reference)
#include <cuda_runtime.h>

// Problem constants
#define BT     16384
#define S_DIM  256
#define O_DIM  128
#define N_DIM  32
#define NQ_DIM 64
#define NOUT   160
#define MASK_VAL (-999999.0f)
#define INV_SQRT_E 0.17677669529663687f

#define TILE_ROWS 32          // rows per CTA
#define NTILES (BT / TILE_ROWS)   // 512

typedef unsigned long long ull;

// ---------------- packed f32x2 helpers ----------------
static __device__ __forceinline__ ull fma2(ull a, ull b, ull c) {
    ull d;
    asm("fma.rn.f32x2 %0, %1, %2, %3;" : "=l"(d) : "l"(a), "l"(b), "l"(c));
    return d;
}
static __device__ __forceinline__ ull dup2(float w) {
    ull d;
    asm("mov.b64 %0, {%1, %1};" : "=l"(d) : "f"(w));
    return d;
}
static __device__ __forceinline__ float lo2(ull v) {
    return __uint_as_float((unsigned int)v);
}
static __device__ __forceinline__ float hi2(ull v) {
    return __uint_as_float((unsigned int)(v >> 32));
}

// ---------------- cp.async helpers ----------------
static __device__ __forceinline__ void cp16(void* dst, const void* src) {
    unsigned s = (unsigned)__cvta_generic_to_shared(dst);
    asm volatile("cp.async.cg.shared.global [%0], [%1], 16;" :: "r"(s), "l"(src));
}
#define CP_COMMIT() asm volatile("cp.async.commit_group;")
#define CP_WAIT1()  asm volatile("cp.async.wait_group 1;")
#define CP_WAIT0()  asm volatile("cp.async.wait_group 0;")

// ---------------- fused smem ----------------
struct FS {
    float qh[TILE_ROWS * 128];   // 16384B  relu(st@[Wq;Sw1]^T), q part
    float p[8 * 512];            // 16384B  p for current 8-row batch
    float part[8][4][32];        //  4096B
    float att[128];
    float wsum[32];
    float qv[32];
    float vs[TILE_ROWS];         // bias MLP output per row
    union {
        struct { float As[32 * 34]; float Ws[NOUT * 33]; } a;       // 25472B
        struct { float4 ob[2][32 * 33]; float4 zb[2][32 * 17]; } d; // 51200B
    } u;
};
#define FS_SMEM ((int)sizeof(FS))   // ~88.9KB -> 2 CTAs/SM

__global__ void __launch_bounds__(256, 2) fused_all(
        const float* __restrict__ z,
        const float* __restrict__ st,
        const float* __restrict__ obs,
        const float* __restrict__ Wq,
        const float* __restrict__ Wk,
        const float* __restrict__ Sw1,
        const float* __restrict__ Sb1,
        const float* __restrict__ Sw2,
        const float* __restrict__ Sb2,
        float* __restrict__ out) {
    extern __shared__ char smraw[];
    FS* S = (FS*)smraw;

    const int tid = threadIdx.x;
    const int rt  = tid >> 5;      // warp 0-7
    const int ct  = tid & 31;      // lane
    const int row0 = blockIdx.x * TILE_ROWS;

    // ================= Phase A: qh = relu([Wq;Sw1] @ st^T), v = MLP =================
    {
        float* As = S->u.a.As;     // [32 k][34]
        float* Ws = S->u.a.Ws;     // [160 n][33]

        ull acc[2][5];
#pragma unroll
        for (int i = 0; i < 2; i++)
#pragma unroll
            for (int j = 0; j < 5; j++) acc[i][j] = 0ULL;

        for (int kc = 0; kc < S_DIM; kc += 32) {
            __syncthreads();
            {   // stage A transposed: 256 float4, one per thread
                int row = tid >> 3, kq = tid & 7;
                float4 v = *(const float4*)(st + (size_t)(row0 + row) * S_DIM + kc + 4 * kq);
                As[(4 * kq + 0) * 34 + row] = v.x;
                As[(4 * kq + 1) * 34 + row] = v.y;
                As[(4 * kq + 2) * 34 + row] = v.z;
                As[(4 * kq + 3) * 34 + row] = v.w;
            }
            for (int i = tid; i < (NOUT * 32) / 4; i += 256) {   // 1280 float4
                int n = i >> 3, kq = i & 7;
                const float* src = (n < 128) ? (Wq + n * S_DIM) : (Sw1 + (n - 128) * S_DIM);
                float4 v = *(const float4*)(src + kc + 4 * kq);
                Ws[n * 33 + 4 * kq + 0] = v.x;
                Ws[n * 33 + 4 * kq + 1] = v.y;
                Ws[n * 33 + 4 * kq + 2] = v.z;
                Ws[n * 33 + 4 * kq + 3] = v.w;
            }
            __syncthreads();
#pragma unroll 8
            for (int kk = 0; kk < 32; kk++) {
                ull b0 = dup2(Ws[(ct)       * 33 + kk]);
                ull b1 = dup2(Ws[(ct + 32)  * 33 + kk]);
                ull b2 = dup2(Ws[(ct + 64)  * 33 + kk]);
                ull b3 = dup2(Ws[(ct + 96)  * 33 + kk]);
                ull b4 = dup2(Ws[(ct + 128) * 33 + kk]);
                const float* ar = As + kk * 34 + rt * 4;
                ull a0 = *(const ull*)(ar);
                ull a1 = *(const ull*)(ar + 2);
                acc[0][0] = fma2(a0, b0, acc[0][0]);
                acc[1][0] = fma2(a1, b0, acc[1][0]);
                acc[0][1] = fma2(a0, b1, acc[0][1]);
                acc[1][1] = fma2(a1, b1, acc[1][1]);
                acc[0][2] = fma2(a0, b2, acc[0][2]);
                acc[1][2] = fma2(a1, b2, acc[1][2]);
                acc[0][3] = fma2(a0, b3, acc[0][3]);
                acc[1][3] = fma2(a1, b3, acc[1][3]);
                acc[0][4] = fma2(a0, b4, acc[0][4]);
                acc[1][4] = fma2(a1, b4, acc[1][4]);
            }
        }

        const float b1c = Sb1[ct];
        const float w2c = Sw2[ct];
        const float b2c = Sb2[0];
#pragma unroll
        for (int i = 0; i < 2; i++) {
            int lr = rt * 4 + 2 * i;          // local rows lr, lr+1
#pragma unroll
            for (int j = 0; j < 4; j++) {
                S->qh[lr * 128 + ct + 32 * j]       = fmaxf(lo2(acc[i][j]), 0.0f);
                S->qh[(lr + 1) * 128 + ct + 32 * j] = fmaxf(hi2(acc[i][j]), 0.0f);
            }
            float h0 = fmaxf(lo2(acc[i][4]) + b1c, 0.0f) * w2c;
            float h1 = fmaxf(hi2(acc[i][4]) + b1c, 0.0f) * w2c;
#pragma unroll
            for (int d = 16; d > 0; d >>= 1) {
                h0 += __shfl_xor_sync(0xffffffffu, h0, d);
                h1 += __shfl_xor_sync(0xffffffffu, h1, d);
            }
            if (ct == 0) {
                S->vs[lr]     = h0 + b2c;
                S->vs[lr + 1] = h1 + b2c;
            }
        }
    }
    __syncthreads();   // qh/vs ready; As/Ws dead -> ob/zb union region usable

    // ---- prefetch (ob + z) for local row lr into buffer b ----
    auto prefetch = [&](int b, int lr) {
        size_t r = (size_t)(row0 + lr);
        const float4* obr4 = (const float4*)(obs + r * (size_t)(N_DIM * O_DIM));
        const float4* zr4  = (const float4*)(z + r * (size_t)(N_DIM * NQ_DIM));
#pragma unroll
        for (int seg = 0; seg < 4; seg++) {           // ob: 1024 f4
            int i = tid + 256 * seg;
            int n = i >> 5, c = i & 31;
            cp16(&S->u.d.ob[b][n * 33 + c], obr4 + i);
        }
#pragma unroll
        for (int seg = 0; seg < 2; seg++) {           // zb: 512 f4
            int i = tid + 256 * seg;
            int n = i >> 4, jq = i & 15;
            cp16(&S->u.d.zb[b][n * 17 + jq], zr4 + i);
        }
    };
    prefetch(0, 0);
    CP_COMMIT();

    const int h4 = rt & 3;        // head for phase B
    const int hf = rt >> 2;       // o-half for phase B

    for (int batch = 0; batch < 4; batch++) {
        const int rb = batch * 8;

        // ============ Phase B: p[rr][512] for rows rb..rb+7 ============
        // warp = (head h4, o-half hf); lane ct = o-pair; Wk from global (L2-hot)
        {
            ull accp[8];
#pragma unroll
            for (int rr = 0; rr < 8; rr++) accp[rr] = 0ULL;
#pragma unroll 4
            for (int e = 0; e < 32; e++) {
                ull bv = *(const ull*)(Wk + (size_t)(h4 * 32 + e) * 128 + hf * 64 + 2 * ct);
#pragma unroll
                for (int rr = 0; rr < 8; rr++) {
                    ull a = dup2(S->qh[(rb + rr) * 128 + h4 * 32 + e]);
                    accp[rr] = fma2(a, bv, accp[rr]);
                }
            }
#pragma unroll
            for (int rr = 0; rr < 8; rr++)
                *(ull*)&S->p[rr * 512 + h4 * 128 + hf * 64 + 2 * ct] = accp[rr];
        }
        __syncthreads();   // p ready (and prior batch's readers finished earlier)

        // ============ Phase C/D: per-row attention (R15 structure) ============
        for (int j = 0; j < 8; j++) {
            const int lr = rb + j;
            const int b = lr & 1;
            if (lr + 1 < TILE_ROWS) {
                prefetch(b ^ 1, lr + 1);
                CP_COMMIT();
                CP_WAIT1();
            } else {
                CP_WAIT0();
            }
            __syncthreads();

            const int n  = ct;
            const int oc = rt;

            // q_vals over 2 warps
            if (tid < 64) {
                int n2 = tid >> 1, half = tid & 1;
                const float4* zrow = &S->u.d.zb[b][n2 * 17 + half * 8];
                float s = 0.0f;
#pragma unroll
                for (int jj = 0; jj < 8; jj++) {
                    float4 v = zrow[jj];
                    s += v.x + v.y + v.z + v.w;
                }
                s += __shfl_xor_sync(0xffffffffu, s, 1);
                if (half == 0) S->qv[n2] = s * (1.0f / 64.0f);
            }

            // scores: thread (n, oc) covers o in [oc*16, oc*16+16)
            const float4* obn = &S->u.d.ob[b][n * 33 + oc * 4];
            const float4* pbv = (const float4*)(S->p + j * 512);
            float pa0 = 0.0f, pa1 = 0.0f, pa2 = 0.0f, pa3 = 0.0f;
#pragma unroll
            for (int o4 = 0; o4 < 4; o4++) {
                float4 x  = obn[o4];
                float4 p0 = pbv[0  + oc * 4 + o4];
                float4 p1 = pbv[32 + oc * 4 + o4];
                float4 p2 = pbv[64 + oc * 4 + o4];
                float4 p3 = pbv[96 + oc * 4 + o4];
                pa0 += x.x * p0.x + x.y * p0.y + x.z * p0.z + x.w * p0.w;
                pa1 += x.x * p1.x + x.y * p1.y + x.z * p1.z + x.w * p1.w;
                pa2 += x.x * p2.x + x.y * p2.y + x.z * p2.z + x.w * p2.w;
                pa3 += x.x * p3.x + x.y * p3.y + x.z * p3.z + x.w * p3.w;
            }
            S->part[oc][0][n] = pa0;
            S->part[oc][1][n] = pa1;
            S->part[oc][2][n] = pa2;
            S->part[oc][3][n] = pa3;
            __syncthreads();

            // softmax: warps 0-3, warp hh handles head hh
            if (tid < 128) {
                const int hh = rt;
                float s = 0.0f;
#pragma unroll
                for (int c = 0; c < 8; c++) s += S->part[c][hh][n];
                s *= INV_SQRT_E;
                if (S->qv[n] <= MASK_VAL) s = MASK_VAL;
                float m = s;
#pragma unroll
                for (int d = 16; d > 0; d >>= 1)
                    m = fmaxf(m, __shfl_xor_sync(0xffffffffu, m, d));
                float ex = __expf(s - m);
                float ssum = ex;
#pragma unroll
                for (int d = 16; d > 0; d >>= 1)
                    ssum += __shfl_xor_sync(0xffffffffu, ssum, d);
                S->att[hh * 32 + n] = ex / ssum;
            }
            __syncthreads();

            if (tid < 32)
                S->wsum[tid] = S->att[tid] + S->att[32 + tid]
                             + S->att[64 + tid] + S->att[96 + tid] + 1e-10f;
            __syncthreads();

            // out[q] = sum_n w[n]*z[n][q] + 32*v
            if (tid < 64) {
                const float* zsf = (const float*)S->u.d.zb[b];  // row stride 68 floats
                float acc = (float)N_DIM * S->vs[lr];
#pragma unroll
                for (int nn = 0; nn < 32; nn++)
                    acc = fmaf(S->wsum[nn], zsf[nn * 68 + tid], acc);
                out[(size_t)(row0 + lr) * 64 + tid] = acc;
            }
            __syncthreads();   // buffer b + part/att/wsum reuse guard
        }
    }
}

// ==================== launch ====================
extern "C" void kernel_launch(void* const* d_in, const int* in_sizes, int n_in,
                              void* d_out, int out_size) {
    (void)in_sizes; (void)n_in; (void)out_size;
    const float* z   = (const float*)d_in[0];
    const float* st  = (const float*)d_in[1];
    const float* obs = (const float*)d_in[2];
    const float* Wq  = (const float*)d_in[3];
    const float* Wk  = (const float*)d_in[4];
    const float* Sw1 = (const float*)d_in[5];
    const float* Sb1 = (const float*)d_in[6];
    const float* Sw2 = (const float*)d_in[7];
    const float* Sb2 = (const float*)d_in[8];
    float* out = (float*)d_out;

    cudaFuncSetAttribute(fused_all, cudaFuncAttributeMaxDynamicSharedMemorySize, FS_SMEM);
    fused_all<<<NTILES, 256, FS_SMEM>>>(z, st, obs, Wq, Wk, Sw1, Sb1, Sw2, Sb2, out);
}

// round 17
// speedup vs baseline: 1.1614x; 1.1614x over previous
#include <cuda_runtime.h>

// Problem constants
#define BT     16384
#define S_DIM  256
#define O_DIM  128
#define N_DIM  32
#define NQ_DIM 64
#define NOUT   160
#define MASK_VAL (-999999.0f)
#define INV_SQRT_E 0.17677669529663687f

typedef unsigned long long ull;

// Scratch (device globals; no allocation allowed)
__device__ float g_qh[(size_t)BT * 128];
__device__ float g_v[BT];
__device__ float g_p[(size_t)BT * 512];

// ---------------- packed f32x2 helpers ----------------
static __device__ __forceinline__ ull fma2(ull a, ull b, ull c) {
    ull d;
    asm("fma.rn.f32x2 %0, %1, %2, %3;" : "=l"(d) : "l"(a), "l"(b), "l"(c));
    return d;
}
static __device__ __forceinline__ ull dup2(float w) {
    ull d;
    asm("mov.b64 %0, {%1, %1};" : "=l"(d) : "f"(w));
    return d;
}
static __device__ __forceinline__ float lo2(ull v) {
    return __uint_as_float((unsigned int)v);
}
static __device__ __forceinline__ float hi2(ull v) {
    return __uint_as_float((unsigned int)(v >> 32));
}

// ---------------- cp.async helpers ----------------
static __device__ __forceinline__ void cp16(void* dst, const void* src) {
    unsigned s = (unsigned)__cvta_generic_to_shared(dst);
    asm volatile("cp.async.cg.shared.global [%0], [%1], 16;" :: "r"(s), "l"(src));
}
static __device__ __forceinline__ void cp4(void* dst, const void* src) {
    unsigned s = (unsigned)__cvta_generic_to_shared(dst);
    asm volatile("cp.async.ca.shared.global [%0], [%1], 4;" :: "r"(s), "l"(src));
}
#define CP_COMMIT() asm volatile("cp.async.commit_group;")
#define CP_WAIT1()  asm volatile("cp.async.wait_group 1;")
#define CP_WAIT0()  asm volatile("cp.async.wait_group 0;")

// ==================== K1 (R11/R15 exact, ~43us measured) ====================
#define K1_BM 64
#define K1_KC 32
#define K1_AS 66
#define K1_WS 33
#define K1_SMEM (K1_KC*K1_AS*4 + NOUT*K1_WS*4)   // 29568B

__global__ void __launch_bounds__(256, 2) k1_qh(
        const float* __restrict__ st,
        const float* __restrict__ Wq,
        const float* __restrict__ Sw1,
        const float* __restrict__ Sb1,
        const float* __restrict__ Sw2,
        const float* __restrict__ Sb2) {
    extern __shared__ float smem[];
    float* As = smem;                          // [32 k][66]
    float* Ws = smem + K1_KC * K1_AS;          // [160 n][33]

    const int tid = threadIdx.x;
    const int rt  = tid >> 5;
    const int ct  = tid & 31;
    const int row0 = blockIdx.x * K1_BM;

    const float* wp0 = Ws + (ct)       * K1_WS;
    const float* wp1 = Ws + (ct + 32)  * K1_WS;
    const float* wp2 = Ws + (ct + 64)  * K1_WS;
    const float* wp3 = Ws + (ct + 96)  * K1_WS;
    const float* wp4 = Ws + (ct + 128) * K1_WS;

    ull acc[4][5];
#pragma unroll
    for (int i = 0; i < 4; i++)
#pragma unroll
        for (int j = 0; j < 5; j++) acc[i][j] = 0ULL;

    for (int kc = 0; kc < S_DIM; kc += K1_KC) {
        __syncthreads();
#pragma unroll
        for (int s = 0; s < 2; s++) {
            int idx = tid + 256 * s;
            int row = idx >> 3, kq = idx & 7;
            float4 v = *(const float4*)(st + (size_t)(row0 + row) * S_DIM + kc + 4 * kq);
            As[(4 * kq + 0) * K1_AS + row] = v.x;
            As[(4 * kq + 1) * K1_AS + row] = v.y;
            As[(4 * kq + 2) * K1_AS + row] = v.z;
            As[(4 * kq + 3) * K1_AS + row] = v.w;
        }
        for (int i = tid; i < (NOUT * K1_KC) / 4; i += 256) {
            int n = i >> 3, kq = i & 7;
            const float* src = (n < 128) ? (Wq + n * S_DIM) : (Sw1 + (n - 128) * S_DIM);
            float4 v = *(const float4*)(src + kc + 4 * kq);
            Ws[n * K1_WS + 4 * kq + 0] = v.x;
            Ws[n * K1_WS + 4 * kq + 1] = v.y;
            Ws[n * K1_WS + 4 * kq + 2] = v.z;
            Ws[n * K1_WS + 4 * kq + 3] = v.w;
        }
        __syncthreads();

        float c0 = wp0[0], c1 = wp1[0], c2 = wp2[0], c3 = wp3[0], c4 = wp4[0];
        const float* ar0 = As + rt * 8;
        ull a0 = *(const ull*)(ar0);
        ull a1 = *(const ull*)(ar0 + 2);
        ull a2 = *(const ull*)(ar0 + 4);
        ull a3 = *(const ull*)(ar0 + 6);
#pragma unroll
        for (int kk = 0; kk < K1_KC; kk++) {
            float d0, d1, d2, d3, d4;
            ull e0, e1, e2, e3;
            if (kk < K1_KC - 1) {
                d0 = wp0[kk + 1]; d1 = wp1[kk + 1]; d2 = wp2[kk + 1];
                d3 = wp3[kk + 1]; d4 = wp4[kk + 1];
                const float* arn = As + (kk + 1) * K1_AS + rt * 8;
                e0 = *(const ull*)(arn);
                e1 = *(const ull*)(arn + 2);
                e2 = *(const ull*)(arn + 4);
                e3 = *(const ull*)(arn + 6);
            } else {
                d0 = d1 = d2 = d3 = d4 = 0.0f;
                e0 = e1 = e2 = e3 = 0ULL;
            }
            ull b0 = dup2(c0), b1 = dup2(c1), b2 = dup2(c2),
                b3 = dup2(c3), b4 = dup2(c4);
            acc[0][0] = fma2(a0, b0, acc[0][0]);
            acc[1][0] = fma2(a1, b0, acc[1][0]);
            acc[2][0] = fma2(a2, b0, acc[2][0]);
            acc[3][0] = fma2(a3, b0, acc[3][0]);
            acc[0][1] = fma2(a0, b1, acc[0][1]);
            acc[1][1] = fma2(a1, b1, acc[1][1]);
            acc[2][1] = fma2(a2, b1, acc[2][1]);
            acc[3][1] = fma2(a3, b1, acc[3][1]);
            acc[0][2] = fma2(a0, b2, acc[0][2]);
            acc[1][2] = fma2(a1, b2, acc[1][2]);
            acc[2][2] = fma2(a2, b2, acc[2][2]);
            acc[3][2] = fma2(a3, b2, acc[3][2]);
            acc[0][3] = fma2(a0, b3, acc[0][3]);
            acc[1][3] = fma2(a1, b3, acc[1][3]);
            acc[2][3] = fma2(a2, b3, acc[2][3]);
            acc[3][3] = fma2(a3, b3, acc[3][3]);
            acc[0][4] = fma2(a0, b4, acc[0][4]);
            acc[1][4] = fma2(a1, b4, acc[1][4]);
            acc[2][4] = fma2(a2, b4, acc[2][4]);
            acc[3][4] = fma2(a3, b4, acc[3][4]);
            c0 = d0; c1 = d1; c2 = d2; c3 = d3; c4 = d4;
            a0 = e0; a1 = e1; a2 = e2; a3 = e3;
        }
    }

    const float b1c = Sb1[ct];
    const float w2c = Sw2[ct];
    const float b2c = Sb2[0];
#pragma unroll
    for (int i = 0; i < 4; i++) {
        int r0 = row0 + rt * 8 + 2 * i;
#pragma unroll
        for (int j = 0; j < 4; j++) {
            g_qh[(size_t)r0 * 128 + ct + 32 * j]       = fmaxf(lo2(acc[i][j]), 0.0f);
            g_qh[(size_t)(r0 + 1) * 128 + ct + 32 * j] = fmaxf(hi2(acc[i][j]), 0.0f);
        }
        float h0 = fmaxf(lo2(acc[i][4]) + b1c, 0.0f) * w2c;
        float h1 = fmaxf(hi2(acc[i][4]) + b1c, 0.0f) * w2c;
#pragma unroll
        for (int d = 16; d > 0; d >>= 1) {
            h0 += __shfl_xor_sync(0xffffffffu, h0, d);
            h1 += __shfl_xor_sync(0xffffffffu, h1, d);
        }
        if (ct == 0) {
            g_v[r0]     = h0 + b2c;
            g_v[r0 + 1] = h1 + b2c;
        }
    }
}

// ==================== K2 (R11/R15 exact) ====================
#define K2_BM 32

__global__ void __launch_bounds__(256) k2_p(const float* __restrict__ Wk) {
    __shared__ float qh_s[K2_BM * 128];

    const int tid = threadIdx.x;
    const int rt  = tid >> 5;
    const int ct  = tid & 31;
    const int row0 = blockIdx.x * K2_BM;

#pragma unroll
    for (int s = 0; s < 4; s++) {
        int i = tid + 256 * s;
        ((float4*)qh_s)[i] = *(const float4*)(g_qh + (size_t)row0 * 128 + 4 * i);
    }
    __syncthreads();

    const ull* wkp = (const ull*)Wk;
    ull* gp2 = (ull*)g_p;
#pragma unroll
    for (int h = 0; h < 4; h++) {
        ull acc[4][2];
#pragma unroll
        for (int rr = 0; rr < 4; rr++) { acc[rr][0] = 0ULL; acc[rr][1] = 0ULL; }

#pragma unroll 4
        for (int e4 = 0; e4 < 8; e4++) {
            float4 aq[4];
#pragma unroll
            for (int rr = 0; rr < 4; rr++)
                aq[rr] = *(const float4*)(qh_s + (rt * 4 + rr) * 128 + h * 32 + 4 * e4);
#pragma unroll
            for (int q = 0; q < 4; q++) {
                const ull* brow = wkp + (size_t)(h * 32 + 4 * e4 + q) * 64;
                ull b0 = brow[ct];
                ull b1 = brow[32 + ct];
#pragma unroll
                for (int rr = 0; rr < 4; rr++) {
                    float av = (q == 0) ? aq[rr].x : (q == 1) ? aq[rr].y
                             : (q == 2) ? aq[rr].z : aq[rr].w;
                    ull a = dup2(av);
                    acc[rr][0] = fma2(a, b0, acc[rr][0]);
                    acc[rr][1] = fma2(a, b1, acc[rr][1]);
                }
            }
        }
#pragma unroll
        for (int rr = 0; rr < 4; rr++) {
            size_t base = (size_t)(row0 + rt * 4 + rr) * 256 + h * 64;
            gp2[base + ct]      = acc[rr][0];
            gp2[base + 32 + ct] = acc[rr][1];
        }
    }
}

// ==================== K3: R15 compute, single-buffer z (52KB -> 4 CTAs/SM) ====================
#define K3_ROWS 8

struct K3S {
    float4 ob[2][32 * 33];     // 33792B : ob[n][c] padded 33
    float4 zb[32 * 17];        //  8704B : z[n][jq] padded 17 (SINGLE buffer)
    float4 pb[2][128];         //  4096B
    float  part_s[8][4][32];   //  4096B
    float  att_s[128];
    float  w_s[32];
    float  qv_s[32];
    float  vbuf[2];
};
#define K3_SMEM ((int)sizeof(K3S))   // ~52.1KB -> 4 CTAs/SM

__global__ void __launch_bounds__(256, 4) k3_out(
        const float* __restrict__ z,
        const float* __restrict__ obs,
        float* __restrict__ out) {
    extern __shared__ char sm3[];
    K3S* S = (K3S*)sm3;

    const int tid = threadIdx.x;
    const size_t r0 = (size_t)blockIdx.x * K3_ROWS;
    const float4* gp4 = (const float4*)g_p;

    // ob + p + v prefetch (group A_r)
    auto prefetch_ob = [&](int b, size_t r) {
        const float4* obr4 = (const float4*)(obs + r * (size_t)(N_DIM * O_DIM));
#pragma unroll
        for (int seg = 0; seg < 4; seg++) {           // ob: 1024 f4
            int i = tid + 256 * seg;
            int n = i >> 5, c = i & 31;
            cp16(&S->ob[b][n * 33 + c], obr4 + i);
        }
        if (tid < 128) cp16(&S->pb[b][tid], gp4 + r * 128 + tid);
        if (tid == 0) cp4(&S->vbuf[b], g_v + r);
    };
    // z prefetch into the single zb buffer (group Z_r)
    auto prefetch_z = [&](size_t r) {
        const float4* zr4 = (const float4*)(z + r * (size_t)(N_DIM * NQ_DIM));
#pragma unroll
        for (int seg = 0; seg < 2; seg++) {           // zb: 512 f4
            int i = tid + 256 * seg;
            int n = i >> 4, jq = i & 15;
            cp16(&S->zb[n * 17 + jq], zr4 + i);
        }
    };

    prefetch_ob(0, r0);  CP_COMMIT();      // A_0
    prefetch_z(r0);      CP_COMMIT();      // Z_0

    const int n  = tid & 31;
    const int oc = tid >> 5;

    for (int i = 0; i < K3_ROWS; i++) {
        const int b = i & 1;
        const size_t r = r0 + i;
        if (i + 1 < K3_ROWS) {
            prefetch_ob(b ^ 1, r + 1);
            CP_COMMIT();                   // pending: A_i, Z_i, A_{i+1}
            CP_WAIT1();                    // A_i and Z_i complete
        } else {
            CP_WAIT0();
        }
        __syncthreads();

        // q_vals over 2 warps
        if (tid < 64) {
            int n2 = tid >> 1, hf = tid & 1;
            const float4* zrow = &S->zb[n2 * 17 + hf * 8];
            float s = 0.0f;
#pragma unroll
            for (int j = 0; j < 8; j++) {
                float4 v = zrow[j];
                s += v.x + v.y + v.z + v.w;
            }
            s += __shfl_xor_sync(0xffffffffu, s, 1);
            if (hf == 0) S->qv_s[n2] = s * (1.0f / 64.0f);
        }

        // scores: thread (n, oc) covers o in [oc*16, oc*16+16)
        const float4* obn = &S->ob[b][n * 33 + oc * 4];
        const float4* pbv = S->pb[b];
        float pa0 = 0.0f, pa1 = 0.0f, pa2 = 0.0f, pa3 = 0.0f;
#pragma unroll
        for (int o4 = 0; o4 < 4; o4++) {
            float4 x  = obn[o4];
            float4 p0 = pbv[0  + oc * 4 + o4];
            float4 p1 = pbv[32 + oc * 4 + o4];
            float4 p2 = pbv[64 + oc * 4 + o4];
            float4 p3 = pbv[96 + oc * 4 + o4];
            pa0 += x.x * p0.x + x.y * p0.y + x.z * p0.z + x.w * p0.w;
            pa1 += x.x * p1.x + x.y * p1.y + x.z * p1.z + x.w * p1.w;
            pa2 += x.x * p2.x + x.y * p2.y + x.z * p2.z + x.w * p2.w;
            pa3 += x.x * p3.x + x.y * p3.y + x.z * p3.z + x.w * p3.w;
        }
        S->part_s[oc][0][n] = pa0;
        S->part_s[oc][1][n] = pa1;
        S->part_s[oc][2][n] = pa2;
        S->part_s[oc][3][n] = pa3;
        __syncthreads();

        // softmax: warps 0-3, warp h handles head h
        if (tid < 128) {
            const int h = oc;
            float s = 0.0f;
#pragma unroll
            for (int c = 0; c < 8; c++) s += S->part_s[c][h][n];
            s *= INV_SQRT_E;
            if (S->qv_s[n] <= MASK_VAL) s = MASK_VAL;
            float m = s;
#pragma unroll
            for (int d = 16; d > 0; d >>= 1)
                m = fmaxf(m, __shfl_xor_sync(0xffffffffu, m, d));
            float ex = __expf(s - m);
            float ssum = ex;
#pragma unroll
            for (int d = 16; d > 0; d >>= 1)
                ssum += __shfl_xor_sync(0xffffffffu, ssum, d);
            S->att_s[h * 32 + n] = ex / ssum;
        }
        __syncthreads();

        if (tid < 32)
            S->w_s[tid] = S->att_s[tid] + S->att_s[32 + tid]
                        + S->att_s[64 + tid] + S->att_s[96 + tid] + 1e-10f;
        __syncthreads();

        // out[q] = sum_n w[n]*z[n][q] + 32*v   (zb floats, row stride 68)
        if (tid < 64) {
            const float* zsf = (const float*)S->zb;
            float acc = (float)N_DIM * S->vbuf[b];
#pragma unroll
            for (int nn = 0; nn < 32; nn++)
                acc = fmaf(S->w_s[nn], zsf[nn * 68 + tid], acc);
            out[r * 64 + tid] = acc;
        }
        __syncthreads();                   // all zb readers done

        if (i + 1 < K3_ROWS) {
            prefetch_z(r + 1);
            CP_COMMIT();                   // Z_{i+1}
        }
    }
}

// ==================== launch ====================
extern "C" void kernel_launch(void* const* d_in, const int* in_sizes, int n_in,
                              void* d_out, int out_size) {
    (void)in_sizes; (void)n_in; (void)out_size;
    const float* z   = (const float*)d_in[0];
    const float* st  = (const float*)d_in[1];
    const float* obs = (const float*)d_in[2];
    const float* Wq  = (const float*)d_in[3];
    const float* Wk  = (const float*)d_in[4];
    const float* Sw1 = (const float*)d_in[5];
    const float* Sb1 = (const float*)d_in[6];
    const float* Sw2 = (const float*)d_in[7];
    const float* Sb2 = (const float*)d_in[8];
    float* out = (float*)d_out;

    cudaFuncSetAttribute(k1_qh,  cudaFuncAttributeMaxDynamicSharedMemorySize, K1_SMEM);
    cudaFuncSetAttribute(k3_out, cudaFuncAttributeMaxDynamicSharedMemorySize, K3_SMEM);

    k1_qh<<<BT / K1_BM, 256, K1_SMEM>>>(st, Wq, Sw1, Sb1, Sw2, Sb2);
    k2_p<<<BT / K2_BM, 256>>>(Wk);
    k3_out<<<BT / K3_ROWS, 256, K3_SMEM>>>(z, obs, out);
}